// round 5
// baseline (speedup 1.0000x reference)
#include <cuda_runtime.h>
#include <math.h>

#define B_ROWS 32768
#define IN_DIM 1024
#define HID    64
#define COMM   256
#define KP     8192

// ---------- scratch (no runtime allocation allowed) ----------
__device__ float  g_h3[B_ROWS * COMM];
__device__ float  g_sample[B_ROWS * COMM];
__device__ float  g_sq[B_ROWS];
__device__ float  g_pn[KP];
__device__ int    g_idx[B_ROWS];
__device__ double g_acc[2];   // [0] = sum (q-s)^2 , [1] = sum (1+lv-mu^2-exp(lv))

// ---------- K0: zero accumulators ----------
__global__ void k_zero() { g_acc[0] = 0.0; g_acc[1] = 0.0; }

// ---------- proto squared norms: warp per proto row ----------
__global__ void k_pn(const float* __restrict__ protos) {
    int row  = blockIdx.x * 8 + (threadIdx.x >> 5);
    int lane = threadIdx.x & 31;
    float a = 0.f;
#pragma unroll
    for (int m = 0; m < 8; m++) {
        float v = protos[row * COMM + lane + 32 * m];
        a = fmaf(v, v, a);
    }
#pragma unroll
    for (int o = 16; o > 0; o >>= 1) a += __shfl_down_sync(0xffffffffu, a, o);
    if (lane == 0) g_pn[row] = a;
}

// ---------- fused MLP: x -> h1 -> relu(h2) -> relu(h3)  (64 rows / block) ----------
__global__ __launch_bounds__(256) void k_mlp(
    const float* __restrict__ x,  const float* __restrict__ Wf, const float* __restrict__ bf,
    const float* __restrict__ W0, const float* __restrict__ b0,
    const float* __restrict__ W1, const float* __restrict__ b1)
{
    __shared__ float bufA[64 * 68];
    __shared__ float bufB[64 * 68];
    const int t  = threadIdx.x;
    const int tx = t & 15, ty = t >> 4;
    const int rowbase = blockIdx.x * 64;

    float* sX = bufA;              // [32][68] k-major (stage 1)
    float* sW = bufA + 32 * 68;    // [32][68]

    // ---- stage 1: h1 = x @ Wf + bf (no relu) ----
    float acc[4][4];
#pragma unroll
    for (int r = 0; r < 4; r++)
#pragma unroll
        for (int c = 0; c < 4; c++) acc[r][c] = 0.f;

    for (int kc = 0; kc < IN_DIM; kc += 32) {
        {   // load x chunk [64 rows][32 k] -> sX[k][row]
            int row = t >> 2, kq = (t & 3) * 8;
            const float* src = &x[(rowbase + row) * IN_DIM + kc + kq];
            float4 v0 = *(const float4*)(src);
            float4 v1 = *(const float4*)(src + 4);
            sX[(kq + 0) * 68 + row] = v0.x; sX[(kq + 1) * 68 + row] = v0.y;
            sX[(kq + 2) * 68 + row] = v0.z; sX[(kq + 3) * 68 + row] = v0.w;
            sX[(kq + 4) * 68 + row] = v1.x; sX[(kq + 5) * 68 + row] = v1.y;
            sX[(kq + 6) * 68 + row] = v1.z; sX[(kq + 7) * 68 + row] = v1.w;
            // load Wf chunk [32 k][64 c] -> sW[k][c]
            int k = t >> 3, cq = (t & 7) * 8;
            const float* ws = &Wf[(kc + k) * HID + cq];
            float4 w0 = *(const float4*)(ws);
            float4 w1 = *(const float4*)(ws + 4);
            *(float4*)&sW[k * 68 + cq]     = w0;
            *(float4*)&sW[k * 68 + cq + 4] = w1;
        }
        __syncthreads();
#pragma unroll 8
        for (int k = 0; k < 32; k++) {
            float a[4], w[4];
#pragma unroll
            for (int r = 0; r < 4; r++) a[r] = sX[k * 68 + ty + 16 * r];
#pragma unroll
            for (int c = 0; c < 4; c++) w[c] = sW[k * 68 + tx + 16 * c];
#pragma unroll
            for (int r = 0; r < 4; r++)
#pragma unroll
                for (int c = 0; c < 4; c++) acc[r][c] = fmaf(a[r], w[c], acc[r][c]);
        }
        __syncthreads();
    }
    // h1 -> bufB[row][col] (bias added last, matching matmul+bias order)
#pragma unroll
    for (int r = 0; r < 4; r++)
#pragma unroll
        for (int c = 0; c < 4; c++)
            bufB[(ty + 16 * r) * 68 + tx + 16 * c] = acc[r][c] + bf[tx + 16 * c];

    // load W0 [64][64] -> bufA[k][c]
    {
        int k = t >> 2, cq = (t & 3) * 16;
#pragma unroll
        for (int i = 0; i < 4; i++)
            *(float4*)&bufA[k * 68 + cq + 4 * i] = *(const float4*)&W0[k * HID + cq + 4 * i];
    }
    __syncthreads();

    // ---- stage 2: h2 = relu(h1 @ W0 + b0) ----
    float acc2[4][4];
#pragma unroll
    for (int r = 0; r < 4; r++)
#pragma unroll
        for (int c = 0; c < 4; c++) acc2[r][c] = 0.f;
#pragma unroll 4
    for (int k = 0; k < 64; k++) {
        float a[4], w[4];
#pragma unroll
        for (int r = 0; r < 4; r++) a[r] = bufB[(ty + 16 * r) * 68 + k];
#pragma unroll
        for (int c = 0; c < 4; c++) w[c] = bufA[k * 68 + tx + 16 * c];
#pragma unroll
        for (int r = 0; r < 4; r++)
#pragma unroll
            for (int c = 0; c < 4; c++) acc2[r][c] = fmaf(a[r], w[c], acc2[r][c]);
    }
    __syncthreads();   // all W0 reads done before overwriting bufA with h2
#pragma unroll
    for (int r = 0; r < 4; r++)
#pragma unroll
        for (int c = 0; c < 4; c++)
            bufA[(ty + 16 * r) * 68 + tx + 16 * c] =
                fmaxf(acc2[r][c] + b0[tx + 16 * c], 0.f);

    // ---- stage 3: h3 = relu(h2 @ W1 + b1), 4 column passes of 64 ----
    for (int cb = 0; cb < COMM; cb += 64) {
        {   // load W1 chunk [64 k][64 c] -> bufB[k][c]  (h1 is dead)
            int k = t >> 2, cq = (t & 3) * 16;
#pragma unroll
            for (int i = 0; i < 4; i++)
                *(float4*)&bufB[k * 68 + cq + 4 * i] =
                    *(const float4*)&W1[k * COMM + cb + cq + 4 * i];
        }
        __syncthreads();
        float acc3[4][4];
#pragma unroll
        for (int r = 0; r < 4; r++)
#pragma unroll
            for (int c = 0; c < 4; c++) acc3[r][c] = 0.f;
#pragma unroll 4
        for (int k = 0; k < 64; k++) {
            float a[4], w[4];
#pragma unroll
            for (int r = 0; r < 4; r++) a[r] = bufA[(ty + 16 * r) * 68 + k];
#pragma unroll
            for (int c = 0; c < 4; c++) w[c] = bufB[k * 68 + tx + 16 * c];
#pragma unroll
            for (int r = 0; r < 4; r++)
#pragma unroll
                for (int c = 0; c < 4; c++) acc3[r][c] = fmaf(a[r], w[c], acc3[r][c]);
        }
#pragma unroll
        for (int r = 0; r < 4; r++)
#pragma unroll
            for (int c = 0; c < 4; c++)
                g_h3[(rowbase + ty + 16 * r) * COMM + cb + tx + 16 * c] =
                    fmaxf(acc3[r][c] + b1[cb + tx + 16 * c], 0.f);
        __syncthreads();
    }
}

// ---------- variational head: mu, logvar, sample, |s|^2, KLD  (16 rows / block) ----------
__global__ __launch_bounds__(256) void k_head(
    const float* __restrict__ eps,
    const float* __restrict__ Wm, const float* __restrict__ bm,
    const float* __restrict__ Wv, const float* __restrict__ bv)
{
    __shared__ float  sH[16 * 256];
    __shared__ double sdk[8];
    const int t = threadIdx.x;
    const int rowbase = blockIdx.x * 16;

    // load h3 tile (coalesced float4)
#pragma unroll
    for (int i = 0; i < 4; i++) {
        int f = i * 256 + t;           // float4 index, 1024 total
        int row = f >> 6, c4 = f & 63;
        *(float4*)&sH[row * 256 + c4 * 4] =
            *(const float4*)&g_h3[(rowbase + row) * COMM + c4 * 4];
    }
    __syncthreads();

    const int c = t;
    float ma[16], la[16];
#pragma unroll
    for (int r = 0; r < 16; r++) { ma[r] = 0.f; la[r] = 0.f; }
    for (int k = 0; k < COMM; k++) {
        float w = Wm[k * COMM + c];
#pragma unroll
        for (int r = 0; r < 16; r++) ma[r] = fmaf(sH[r * 256 + k], w, ma[r]);
    }
    for (int k = 0; k < COMM; k++) {
        float w = Wv[k * COMM + c];
#pragma unroll
        for (int r = 0; r < 16; r++) la[r] = fmaf(sH[r * 256 + k], w, la[r]);
    }
    __syncthreads();   // done reading sH; reuse for s^2 reduction

    const float bmc = bm[c], bvc = bv[c];
    double dk = 0.0;
#pragma unroll
    for (int r = 0; r < 16; r++) {
        float mu = __fadd_rn(ma[r], bmc);
        float lv = __fadd_rn(la[r], bvc);
        float e  = eps[(rowbase + r) * COMM + c];
        float s  = __fadd_rn(mu, __fmul_rn(e, expf(0.5f * lv)));
        g_sample[(rowbase + r) * COMM + c] = s;
        dk += (double)(1.0f + lv - mu * mu - expf(lv));
        sH[r * 256 + c] = s * s;
    }
    __syncthreads();

    // per-row sums of s^2 : warp w handles rows w and w+8
    int w = t >> 5, lane = t & 31;
#pragma unroll
    for (int h = 0; h < 2; h++) {
        int r = w + 8 * h;
        float a = 0.f;
#pragma unroll
        for (int m = 0; m < 8; m++) a += sH[r * 256 + lane + 32 * m];
#pragma unroll
        for (int o = 16; o > 0; o >>= 1) a += __shfl_down_sync(0xffffffffu, a, o);
        if (lane == 0) g_sq[rowbase + r] = a;
    }

    // KLD block reduce (double)
#pragma unroll
    for (int o = 16; o > 0; o >>= 1) dk += __shfl_down_sync(0xffffffffu, dk, o);
    if (lane == 0) sdk[w] = dk;
    __syncthreads();
    if (t == 0) {
        double v = 0.0;
#pragma unroll
        for (int i = 0; i < 8; i++) v += sdk[i];
        atomicAdd(&g_acc[1], v);
    }
}

// ---------- fused distance GEMM + argmin : 128 rows/block, full 8192 protos ----------
__global__ __launch_bounds__(256, 2) void k_dist(const float* __restrict__ protos)
{
    __shared__ float sS[32 * 132];
    __shared__ float sP[32 * 132];
    const int t  = threadIdx.x;
    const int tx = t & 15, ty = t >> 4;
    const int rowbase = blockIdx.x * 128;

    float sq[8];
#pragma unroll
    for (int r = 0; r < 8; r++) sq[r] = g_sq[rowbase + ty * 8 + r];

    float best[8]; int bidx[8];
#pragma unroll
    for (int r = 0; r < 8; r++) { best[r] = 3.4e38f; bidx[r] = 0; }

    for (int jb = 0; jb < KP; jb += 128) {
        float acc[8][8];
#pragma unroll
        for (int r = 0; r < 8; r++)
#pragma unroll
            for (int c = 0; c < 8; c++) acc[r][c] = 0.f;

        for (int kc = 0; kc < COMM; kc += 32) {
#pragma unroll
            for (int i = 0; i < 4; i++) {
                int f = i * 256 + t;           // 1024 float4 per tile
                int row = f >> 3, kq = (f & 7) * 4;
                float4 v = *(const float4*)&g_sample[(rowbase + row) * COMM + kc + kq];
                sS[(kq + 0) * 132 + row] = v.x; sS[(kq + 1) * 132 + row] = v.y;
                sS[(kq + 2) * 132 + row] = v.z; sS[(kq + 3) * 132 + row] = v.w;
                float4 p = *(const float4*)&protos[(jb + row) * COMM + kc + kq];
                sP[(kq + 0) * 132 + row] = p.x; sP[(kq + 1) * 132 + row] = p.y;
                sP[(kq + 2) * 132 + row] = p.z; sP[(kq + 3) * 132 + row] = p.w;
            }
            __syncthreads();
#pragma unroll
            for (int k = 0; k < 32; k++) {
                float4 a0 = *(float4*)&sS[k * 132 + ty * 8];
                float4 a1 = *(float4*)&sS[k * 132 + ty * 8 + 4];
                float4 b0 = *(float4*)&sP[k * 132 + tx * 8];
                float4 b1 = *(float4*)&sP[k * 132 + tx * 8 + 4];
                float a[8] = {a0.x, a0.y, a0.z, a0.w, a1.x, a1.y, a1.z, a1.w};
                float b[8] = {b0.x, b0.y, b0.z, b0.w, b1.x, b1.y, b1.z, b1.w};
#pragma unroll
                for (int r = 0; r < 8; r++)
#pragma unroll
                    for (int c = 0; c < 8; c++)
                        acc[r][c] = fmaf(a[r], b[c], acc[r][c]);
            }
            __syncthreads();
        }
        // epilogue: d = fl(fl(sq+pn) - fl(2*dot)), strict < keeps first min
#pragma unroll
        for (int c = 0; c < 8; c++) {
            int j = jb + tx * 8 + c;
            float pn = __ldg(&g_pn[j]);
#pragma unroll
            for (int r = 0; r < 8; r++) {
                float t1 = __fadd_rn(sq[r], pn);
                float d  = __fadd_rn(t1, -__fmul_rn(2.0f, acc[r][c]));
                if (d < best[r]) { best[r] = d; bidx[r] = j; }
            }
        }
    }
    __syncthreads();

    // cross-tx merge: reuse sS (values) and sP (indices): [128 rows][16 tx]
    float* rv = sS;
    int*   ri = (int*)sP;
#pragma unroll
    for (int r = 0; r < 8; r++) {
        rv[(ty * 8 + r) * 16 + tx] = best[r];
        ri[(ty * 8 + r) * 16 + tx] = bidx[r];
    }
    __syncthreads();
    if (t < 128) {
        float bv = rv[t * 16];
        int   bj = ri[t * 16];
#pragma unroll
        for (int e = 1; e < 16; e++) {
            float v = rv[t * 16 + e];
            int   j = ri[t * 16 + e];
            if (v < bv || (v == bv && j < bj)) { bv = v; bj = j; }
        }
        g_idx[rowbase + t] = bj;
    }
}

// ---------- gather q, write q_st, accumulate (q-s)^2 : 32 rows / block ----------
__global__ __launch_bounds__(256) void k_final(const float* __restrict__ protos,
                                               float* __restrict__ out)
{
    __shared__ double sdk[8];
    const int t = threadIdx.x;
    const int rowbase = blockIdx.x * 32;
    double s2 = 0.0;
    for (int r = 0; r < 32; r++) {
        int row = rowbase + r;
        int idx = g_idx[row];
        float q    = protos[idx * COMM + t];
        float s    = g_sample[row * COMM + t];
        float diff = __fsub_rn(q, s);
        out[row * COMM + t] = __fadd_rn(s, diff);   // straight-through: s + (q - s)
        s2 += (double)diff * (double)diff;
    }
    int w = t >> 5, lane = t & 31;
#pragma unroll
    for (int o = 16; o > 0; o >>= 1) s2 += __shfl_down_sync(0xffffffffu, s2, o);
    if (lane == 0) sdk[w] = s2;
    __syncthreads();
    if (t == 0) {
        double v = 0.0;
#pragma unroll
        for (int i = 0; i < 8; i++) v += sdk[i];
        atomicAdd(&g_acc[0], v);
    }
}

// ---------- scalars ----------
__global__ void k_scalar(float* __restrict__ out, int out_size)
{
    double m   = g_acc[0] / ((double)B_ROWS * (double)COMM);   // mean (q-s)^2
    double kld = -0.5 * g_acc[1] / (double)B_ROWS;
    double total = kld + 1.25 * m;        // KL_WEIGHT*kld + (0.25+1.0)*m
    out[out_size - 2] = (float)total;
    out[out_size - 1] = (float)kld;
}

extern "C" void kernel_launch(void* const* d_in, const int* in_sizes, int n_in,
                              void* d_out, int out_size)
{
    const float* x      = (const float*)d_in[0];
    const float* eps    = (const float*)d_in[1];
    const float* W_feat = (const float*)d_in[2];
    const float* b_feat = (const float*)d_in[3];
    const float* W0     = (const float*)d_in[4];
    const float* b0     = (const float*)d_in[5];
    const float* W1     = (const float*)d_in[6];
    const float* b1     = (const float*)d_in[7];
    const float* W_mu   = (const float*)d_in[8];
    const float* b_mu   = (const float*)d_in[9];
    const float* W_var  = (const float*)d_in[10];
    const float* b_var  = (const float*)d_in[11];
    const float* protos = (const float*)d_in[12];
    float* out = (float*)d_out;

    k_zero<<<1, 1>>>();
    k_pn<<<KP / 8, 256>>>(protos);
    k_mlp<<<B_ROWS / 64, 256>>>(x, W_feat, b_feat, W0, b0, W1, b1);
    k_head<<<B_ROWS / 16, 256>>>(eps, W_mu, b_mu, W_var, b_var);
    k_dist<<<B_ROWS / 128, 256>>>(protos);
    k_final<<<B_ROWS / 32, 256>>>(protos, out);
    k_scalar<<<1, 1>>>(out, out_size);
}